// round 6
// baseline (speedup 1.0000x reference)
#include <cuda_runtime.h>
#include <cstdint>
#include <math.h>

// Problem dims
#define BATCH 256
#define SEQ   512
#define INDIM 32
#define HID   256
#define G3    768      // 3*HID
#define PREDL 96

// ---------------- scratch (static device memory; no allocation) ----------------
__device__ float g_xp0[(size_t)BATCH * SEQ * G3];   // x @ W_ih_l0^T + b_ih_l0
__device__ float g_xp1[(size_t)BATCH * SEQ * G3];   // h1 @ W_ih_l1^T + b_ih_l1
__device__ float g_h1 [(size_t)BATCH * SEQ * HID];  // layer-0 hidden states
__device__ float g_hfin[BATCH * HID];               // final hidden of layer 1

__device__ __forceinline__ float sigmoidf_(float x) { return 1.f / (1.f + expf(-x)); }

// =======================================================================
// Generic tiled GEMM:  C[M,N] = A[M,K] @ W[N,K]^T + bias[N]   (fp32)
// 64x64 block tile, 4x4 per thread, 256 threads.
// =======================================================================
__global__ void gemm_bias(const float* __restrict__ A, const float* __restrict__ W,
                          const float* __restrict__ bias, float* __restrict__ C,
                          int M, int N, int K) {
    __shared__ float As[16][65];
    __shared__ float Bs[16][65];
    const int n0 = blockIdx.x * 64;
    const int m0 = blockIdx.y * 64;
    const int tid = threadIdx.x;
    const int tx = tid & 15, ty = tid >> 4;

    float acc[4][4];
#pragma unroll
    for (int i = 0; i < 4; i++)
#pragma unroll
        for (int j = 0; j < 4; j++) acc[i][j] = 0.f;

    for (int k0 = 0; k0 < K; k0 += 16) {
#pragma unroll
        for (int i = tid; i < 1024; i += 256) {
            int r = i >> 4, c = i & 15;
            As[c][r] = A[(size_t)(m0 + r) * K + k0 + c];
            Bs[c][r] = W[(size_t)(n0 + r) * K + k0 + c];
        }
        __syncthreads();
#pragma unroll
        for (int kk = 0; kk < 16; kk++) {
            float a[4], b[4];
#pragma unroll
            for (int i = 0; i < 4; i++) { a[i] = As[kk][ty * 4 + i]; b[i] = Bs[kk][tx * 4 + i]; }
#pragma unroll
            for (int i = 0; i < 4; i++)
#pragma unroll
                for (int j = 0; j < 4; j++) acc[i][j] += a[i] * b[j];
        }
        __syncthreads();
    }
#pragma unroll
    for (int i = 0; i < 4; i++) {
        int m = m0 + ty * 4 + i;
#pragma unroll
        for (int j = 0; j < 4; j++) {
            int n = n0 + tx * 4 + j;
            C[(size_t)m * N + n] = acc[i][j] + bias[n];
        }
    }
}

// =======================================================================
// GRU recurrence: cluster of 4 CTAs covers the 256 hidden units
// (64 units x 3 gates = 192 gate rows per CTA, W slice resident in SMEM fp32).
// Each cluster handles 8 batch rows for all 512 steps.
// h exchanged per step via DSMEM push + barrier.cluster.
// Grid: 128 CTAs (32 clusters), 128 threads/CTA.
// Thread (u in 0..63, b2 in 0..1): computes gates {r,z,n} of hidden unit
// u_base+u for 4 batch rows (b2*4 .. b2*4+3).
// =======================================================================
#define WSTR 193   // padded smem row stride for W (odd -> conflict-free)
#define GRU_SMEM_FLOATS (256 * WSTR + 2 * 256 * 8 + 192)
#define GRU_SMEM_BYTES  (GRU_SMEM_FLOATS * 4)

__device__ __forceinline__ uint32_t smem_u32(const void* p) {
    return (uint32_t)__cvta_generic_to_shared(p);
}

template <bool WRITE_ALL>
__global__ __launch_bounds__(128, 1) __cluster_dims__(4, 1, 1)
void gru_layer(const float* __restrict__ xp, const float* __restrict__ W_hh,
               const float* __restrict__ b_hh, float* __restrict__ hout) {
    extern __shared__ float smem[];
    float* Wt    = smem;                    // [256][WSTR]  transposed W slice
    float* hbuf  = smem + 256 * WSTR;       // [2][256][8]  double-buffered h
    float* bhh_s = hbuf + 2 * 256 * 8;      // [192]

    const int tid  = threadIdx.x;
    const int u    = tid & 63;
    const int b2   = tid >> 6;       // 0..1
    const int bloc = b2 * 4;
    uint32_t rank;
    asm("mov.u32 %0, %%cluster_ctarank;" : "=r"(rank));
    const int u_base = (int)rank * 64;
    const int gu     = u_base + u;
    const int b0     = (blockIdx.x >> 2) * 8;

    // Load W_hh slice transposed: Wt[k][g*64+u_local] = W_hh[g*256 + u_base + u_local][k]
    for (int idx = tid; idx < 192 * 256; idx += 128) {
        int j = idx >> 8, k = idx & 255;
        int row = ((j >> 6) << 8) + u_base + (j & 63);
        Wt[k * WSTR + j] = W_hh[row * 256 + k];
    }
    for (int j = tid; j < 192; j += 128)
        bhh_s[j] = b_hh[((j >> 6) << 8) + u_base + (j & 63)];
    for (int i = tid; i < 2 * 256 * 8; i += 128) hbuf[i] = 0.f;

    // Cluster barrier: all CTAs' hbuf init done before anyone pushes remote h
    asm volatile("barrier.cluster.arrive.aligned;" ::: "memory");
    asm volatile("barrier.cluster.wait.aligned;" ::: "memory");

    const float bh0 = bhh_s[u], bh1 = bhh_s[64 + u], bh2 = bhh_s[128 + u];

    for (int t = 0; t < SEQ; t++) {
        const int cur = t & 1, nxt = cur ^ 1;

        // precomputed input projection (includes b_ih)
        float xg[3][4];
#pragma unroll
        for (int i = 0; i < 4; i++) {
            const float* xr = xp + ((size_t)(b0 + bloc + i) * SEQ + t) * G3 + gu;
            xg[0][i] = xr[0]; xg[1][i] = xr[256]; xg[2][i] = xr[512];
        }

        float a0[4], a1[4], a2[4];
#pragma unroll
        for (int i = 0; i < 4; i++) { a0[i] = 0.f; a1[i] = 0.f; a2[i] = 0.f; }

        const float4* hb4 = (const float4*)(hbuf + cur * 2048);
        const float*  wp  = Wt + u;
#pragma unroll 4
        for (int k = 0; k < 256; k++) {
            float4 h4 = hb4[k * 2 + b2];                 // broadcast within warp
            float w0 = wp[k * WSTR];
            float w1 = wp[k * WSTR + 64];
            float w2 = wp[k * WSTR + 128];
            a0[0] += w0 * h4.x; a0[1] += w0 * h4.y; a0[2] += w0 * h4.z; a0[3] += w0 * h4.w;
            a1[0] += w1 * h4.x; a1[1] += w1 * h4.y; a1[2] += w1 * h4.z; a1[3] += w1 * h4.w;
            a2[0] += w2 * h4.x; a2[1] += w2 * h4.y; a2[2] += w2 * h4.z; a2[3] += w2 * h4.w;
        }

        float4 hp4 = hb4[gu * 2 + b2];
        float hp[4] = {hp4.x, hp4.y, hp4.z, hp4.w};
        float hn[4];
#pragma unroll
        for (int i = 0; i < 4; i++) {
            float r = sigmoidf_(xg[0][i] + a0[i] + bh0);
            float z = sigmoidf_(xg[1][i] + a1[i] + bh1);
            float n = tanhf(xg[2][i] + r * (a2[i] + bh2));
            hn[i] = (1.f - z) * n + z * hp[i];
        }

        // push updated h slice to all 4 CTAs' next-buffer (including self)
        uint32_t laddr = smem_u32(&hbuf[nxt * 2048 + gu * 8 + bloc]);
#pragma unroll
        for (int p = 0; p < 4; p++) {
            uint32_t raddr;
            asm volatile("mapa.shared::cluster.u32 %0, %1, %2;"
                         : "=r"(raddr) : "r"(laddr), "r"(p));
            asm volatile("st.shared::cluster.f32 [%0], %1;"    :: "r"(raddr), "f"(hn[0]) : "memory");
            asm volatile("st.shared::cluster.f32 [%0+4], %1;"  :: "r"(raddr), "f"(hn[1]) : "memory");
            asm volatile("st.shared::cluster.f32 [%0+8], %1;"  :: "r"(raddr), "f"(hn[2]) : "memory");
            asm volatile("st.shared::cluster.f32 [%0+12], %1;" :: "r"(raddr), "f"(hn[3]) : "memory");
        }

        if (WRITE_ALL) {
#pragma unroll
            for (int i = 0; i < 4; i++)
                hout[((size_t)(b0 + bloc + i) * SEQ + t) * HID + gu] = hn[i];
        } else if (t == SEQ - 1) {
#pragma unroll
            for (int i = 0; i < 4; i++)
                hout[(b0 + bloc + i) * HID + gu] = hn[i];
        }

        asm volatile("barrier.cluster.arrive.aligned;" ::: "memory");
        asm volatile("barrier.cluster.wait.aligned;" ::: "memory");
    }
}

// =======================================================================
// Final projection + 96-step linear state-space decode. 1 block per batch row.
// =======================================================================
__global__ void final_kernel(const float* __restrict__ hfin, const float* __restrict__ Wp,
                             const float* __restrict__ bp, const float* __restrict__ Cm,
                             const float* __restrict__ rld, const float* __restrict__ rtd,
                             const float* __restrict__ rg, const float* __restrict__ om,
                             float* __restrict__ out) {
    __shared__ float hs[256];
    __shared__ float ss[128];
    const int b = blockIdx.x, tid = threadIdx.x;  // 128 threads
    hs[tid]       = hfin[b * 256 + tid];
    hs[tid + 128] = hfin[b * 256 + 128 + tid];
    __syncthreads();

    float acc = bp[tid];
    const float* w = Wp + tid * 256;
#pragma unroll 8
    for (int k = 0; k < 256; k++) acc += w[k] * hs[k];
    ss[tid] = acc;
    __syncthreads();

    if (tid < 32) {
        const int d = tid;
        float s0 = ss[d * 4 + 0], s1 = ss[d * 4 + 1], s2 = ss[d * 4 + 2], s3 = ss[d * 4 + 3];
        const float al = sigmoidf_(rld[d]) * 0.15f + 0.85f;
        const float at = sigmoidf_(rtd[d]) * 0.25f + 0.70f;
        const float g  = sigmoidf_(rg[d])  * 0.20f + 0.80f;
        const float c = cosf(om[d]), sn = sinf(om[d]);
        const float r00 = g * c, r01 = -g * sn, r10 = g * sn, r11 = g * c;
        const float C0 = Cm[d * 4 + 0], C1 = Cm[d * 4 + 1];
        const float C2 = Cm[d * 4 + 2], C3 = Cm[d * 4 + 3];
        float* ob = out + (size_t)b * PREDL * 32 + d;
#pragma unroll 4
        for (int t = 0; t < PREDL; t++) {
            float n0 = s0 * al;
            float n1 = s1 * at;
            float n2 = s2 * r00 + s3 * r10;
            float n3 = s2 * r01 + s3 * r11;
            ob[t * 32] = C0 * n0 + C1 * n1 + C2 * n2 + C3 * n3;
            s0 = n0; s1 = n1; s2 = n2; s3 = n3;
        }
    }
}

// =======================================================================
extern "C" void kernel_launch(void* const* d_in, const int* in_sizes, int n_in,
                              void* d_out, int out_size) {
    const float* x     = (const float*)d_in[0];
    const float* Wih0  = (const float*)d_in[1];
    const float* Whh0  = (const float*)d_in[2];
    const float* bih0  = (const float*)d_in[3];
    const float* bhh0  = (const float*)d_in[4];
    const float* Wih1  = (const float*)d_in[5];
    const float* Whh1  = (const float*)d_in[6];
    const float* bih1  = (const float*)d_in[7];
    const float* bhh1  = (const float*)d_in[8];
    const float* Wproj = (const float*)d_in[9];
    const float* bproj = (const float*)d_in[10];
    const float* Cm    = (const float*)d_in[11];
    const float* rld   = (const float*)d_in[12];
    const float* rtd   = (const float*)d_in[13];
    const float* rg    = (const float*)d_in[14];
    const float* om    = (const float*)d_in[15];
    float* out = (float*)d_out;

    float *xp0, *xp1, *h1, *hfin;
    cudaGetSymbolAddress((void**)&xp0,  g_xp0);
    cudaGetSymbolAddress((void**)&xp1,  g_xp1);
    cudaGetSymbolAddress((void**)&h1,   g_h1);
    cudaGetSymbolAddress((void**)&hfin, g_hfin);

    cudaFuncSetAttribute(gru_layer<true>,  cudaFuncAttributeMaxDynamicSharedMemorySize, GRU_SMEM_BYTES);
    cudaFuncSetAttribute(gru_layer<false>, cudaFuncAttributeMaxDynamicSharedMemorySize, GRU_SMEM_BYTES);

    const int M = BATCH * SEQ;  // 131072
    dim3 ggrid(G3 / 64, M / 64);

    // Phase 1: layer-0 input projection (K=32)
    gemm_bias<<<ggrid, 256>>>(x, Wih0, bih0, xp0, M, G3, INDIM);
    // Phase 2: layer-0 recurrence, write all h1
    gru_layer<true><<<128, 128, GRU_SMEM_BYTES>>>(xp0, Whh0, bhh0, h1);
    // Phase 3: layer-1 input projection (K=256)
    gemm_bias<<<ggrid, 256>>>(h1, Wih1, bih1, xp1, M, G3, HID);
    // Phase 4: layer-1 recurrence, final h only
    gru_layer<false><<<128, 128, GRU_SMEM_BYTES>>>(xp1, Whh1, bhh1, hfin);
    // Phase 5: projection + decode scan
    final_kernel<<<256, 128>>>(hfin, Wproj, bproj, Cm, rld, rtd, rg, om, out);
}

// round 7
// speedup vs baseline: 1.6511x; 1.6511x over previous
#include <cuda_runtime.h>
#include <cstdint>
#include <math.h>

// Problem dims
#define BATCH 256
#define SEQ   512
#define INDIM 32
#define HID   256
#define G3    768      // 3*HID
#define PREDL 96

// ---------------- scratch (static device memory; no allocation) ----------------
__device__ float g_xp0[(size_t)BATCH * SEQ * G3];   // x @ W_ih_l0^T + b_ih_l0
__device__ float g_xp1[(size_t)BATCH * SEQ * G3];   // h1 @ W_ih_l1^T + b_ih_l1
__device__ float g_h1 [(size_t)BATCH * SEQ * HID];  // layer-0 hidden states
__device__ float g_hfin[BATCH * HID];               // final hidden of layer 1

// ---------------- f32x2 packed helpers ----------------
__device__ __forceinline__ unsigned long long pack2(float lo, float hi) {
    unsigned long long r;
    asm("mov.b64 %0, {%1,%2};" : "=l"(r) : "f"(lo), "f"(hi));
    return r;
}
__device__ __forceinline__ void unpack2(unsigned long long v, float& lo, float& hi) {
    asm("mov.b64 {%0,%1}, %2;" : "=f"(lo), "=f"(hi) : "l"(v));
}
__device__ __forceinline__ unsigned long long ffma2(unsigned long long a,
                                                    unsigned long long b,
                                                    unsigned long long c) {
    unsigned long long d;
    asm("fma.rn.f32x2 %0, %1, %2, %3;" : "=l"(d) : "l"(a), "l"(b), "l"(c));
    return d;
}
__device__ __forceinline__ unsigned long long addx2(unsigned long long a,
                                                    unsigned long long b) {
    unsigned long long d;
    asm("add.rn.f32x2 %0, %1, %2;" : "=l"(d) : "l"(a), "l"(b));
    return d;
}

__device__ __forceinline__ float fsig(float x) {
    return __fdividef(1.f, 1.f + __expf(-x));
}
__device__ __forceinline__ float ftanh_(float x) {
    // 1 - 2/(e^{2x}+1): saturates correctly at both ends (no inf/inf)
    return 1.f - __fdividef(2.f, __expf(2.f * x) + 1.f);
}

// =======================================================================
// Generic tiled GEMM:  C[M,N] = A[M,K] @ W[N,K]^T + bias[N]   (fp32, FFMA2)
// 64x64 block tile, 4x4 per thread, 256 threads.
// =======================================================================
__global__ void gemm_bias(const float* __restrict__ A, const float* __restrict__ W,
                          const float* __restrict__ bias, float* __restrict__ C,
                          int M, int N, int K) {
    __shared__ float As[16][68];
    __shared__ float Bs[16][68];
    const int n0 = blockIdx.x * 64;
    const int m0 = blockIdx.y * 64;
    const int tid = threadIdx.x;
    const int tx = tid & 15, ty = tid >> 4;

    unsigned long long accp[4][2];
#pragma unroll
    for (int i = 0; i < 4; i++) { accp[i][0] = 0ull; accp[i][1] = 0ull; }

    for (int k0 = 0; k0 < K; k0 += 16) {
#pragma unroll
        for (int i = tid; i < 1024; i += 256) {
            int r = i >> 4, c = i & 15;
            As[c][r] = A[(size_t)(m0 + r) * K + k0 + c];
            Bs[c][r] = W[(size_t)(n0 + r) * K + k0 + c];
        }
        __syncthreads();
#pragma unroll
        for (int kk = 0; kk < 16; kk++) {
            float4 av = *(const float4*)&As[kk][ty * 4];
            ulonglong2 bv = *(const ulonglong2*)&Bs[kk][tx * 4];
            unsigned long long ap0 = pack2(av.x, av.x);
            unsigned long long ap1 = pack2(av.y, av.y);
            unsigned long long ap2 = pack2(av.z, av.z);
            unsigned long long ap3 = pack2(av.w, av.w);
            accp[0][0] = ffma2(ap0, bv.x, accp[0][0]); accp[0][1] = ffma2(ap0, bv.y, accp[0][1]);
            accp[1][0] = ffma2(ap1, bv.x, accp[1][0]); accp[1][1] = ffma2(ap1, bv.y, accp[1][1]);
            accp[2][0] = ffma2(ap2, bv.x, accp[2][0]); accp[2][1] = ffma2(ap2, bv.y, accp[2][1]);
            accp[3][0] = ffma2(ap3, bv.x, accp[3][0]); accp[3][1] = ffma2(ap3, bv.y, accp[3][1]);
        }
        __syncthreads();
    }
#pragma unroll
    for (int i = 0; i < 4; i++) {
        int m = m0 + ty * 4 + i;
        float a0, a1, a2, a3;
        unpack2(accp[i][0], a0, a1);
        unpack2(accp[i][1], a2, a3);
        int n = n0 + tx * 4;
        float* cp = C + (size_t)m * N + n;
        cp[0] = a0 + bias[n + 0];
        cp[1] = a1 + bias[n + 1];
        cp[2] = a2 + bias[n + 2];
        cp[3] = a3 + bias[n + 3];
    }
}

// =======================================================================
// GRU recurrence v2: cluster of 4 CTAs covers the 256 hidden units.
// 256 threads/CTA: bit0 = k-half, bits1-6 = u (0..63), bit7 = b2 (batch quad).
// Each thread accumulates 3 gates x 4 batch over 128 k with FFMA2 (batch pairs),
// reduces across the k-half lane pair via shfl.bfly, then the even/odd lane of
// each pair finalizes 2 batch rows and pushes them to all 4 CTAs via DSMEM.
// Weight SMEM: k-major, stride 193, +16-float skew between k-halves (1-phase LDS).
// h SMEM: [k][8 batch] float4s with +4-float skew between k-halves.
// =======================================================================
#define WSTR 193
#define WT_FLOATS (256 * WSTR + 16)
#define HB_STRIDE 2052                  // (256*8 + 4) floats per buffer
#define GRU_SMEM_FLOATS (WT_FLOATS + 2 * HB_STRIDE)
#define GRU_SMEM_BYTES  (GRU_SMEM_FLOATS * 4)

__device__ __forceinline__ uint32_t smem_u32(const void* p) {
    return (uint32_t)__cvta_generic_to_shared(p);
}

template <bool WRITE_ALL>
__global__ __launch_bounds__(256, 1) __cluster_dims__(4, 1, 1)
void gru_layer(const float* __restrict__ xp, const float* __restrict__ W_hh,
               const float* __restrict__ b_hh, float* __restrict__ hout) {
    extern __shared__ float smem[];
    float* Wt   = smem;                 // [2 halves][128 k][WSTR] with 16-float skew
    float* hbuf = smem + WT_FLOATS;     // [2][256 k][8 b] with 4-float half-skew

    const int tid  = threadIdx.x;
    const int half = tid & 1;
    const int u    = (tid >> 1) & 63;
    const int b2   = tid >> 7;
    uint32_t rank;
    asm("mov.u32 %0, %%cluster_ctarank;" : "=r"(rank));
    const int gu  = (int)rank * 64 + u;
    const int b0  = (blockIdx.x >> 2) * 8;
    const int myb = b2 * 4 + half * 2;  // this lane finalizes batches myb, myb+1

    // Load W_hh slice transposed+skewed: Wt[k*193 + (k>>7)*16 + j] = W_hh[row(j)][k]
    for (int idx = tid; idx < 192 * 256; idx += 256) {
        int j = idx % 192, k = idx / 192;
        int row = ((j >> 6) << 8) + (int)rank * 64 + (j & 63);
        Wt[k * WSTR + ((k >> 7) << 4) + j] = W_hh[row * 256 + k];
    }
    for (int i = tid; i < 2 * HB_STRIDE; i += 256) hbuf[i] = 0.f;

    const float bh0 = b_hh[gu], bh1 = b_hh[256 + gu], bh2 = b_hh[512 + gu];

    // physical float offset of h[gu][myb] within a buffer
    const int hphys_my = gu * 8 + ((gu >> 7) << 2) + myb;

    // running global pointers for xg of this lane's 2 batch rows
    const float* p0 = xp + ((size_t)(b0 + myb) * SEQ) * G3 + gu;
    const float* p1 = p0 + (size_t)SEQ * G3;

    // cluster barrier: all hbuf init done before anyone pushes / reads
    asm volatile("barrier.cluster.arrive.aligned;" ::: "memory");
    asm volatile("barrier.cluster.wait.aligned;" ::: "memory");

    for (int t = 0; t < SEQ; t++) {
        const int cur = t & 1, nxt = cur ^ 1;

        // prefetch input projections (latency hidden by the k-loop)
        float x0r = p0[0], x0z = p0[256], x0n = p0[512];
        float x1r = p1[0], x1z = p1[256], x1n = p1[512];
        p0 += G3; p1 += G3;

        unsigned long long a0A = 0, a0B = 0, a1A = 0, a1B = 0, a2A = 0, a2B = 0;
        const float* wp = Wt + half * (128 * WSTR + 16) + u;
        const ulonglong2* hb = (const ulonglong2*)(hbuf + cur * HB_STRIDE);
        int hidx = half * 257 + b2;

#pragma unroll 4
        for (int i = 0; i < 128; i++) {
            ulonglong2 h2 = hb[hidx];
            float w0 = wp[0], w1 = wp[64], w2 = wp[128];
            unsigned long long w0p = pack2(w0, w0);
            unsigned long long w1p = pack2(w1, w1);
            unsigned long long w2p = pack2(w2, w2);
            a0A = ffma2(w0p, h2.x, a0A); a0B = ffma2(w0p, h2.y, a0B);
            a1A = ffma2(w1p, h2.x, a1A); a1B = ffma2(w1p, h2.y, a1B);
            a2A = ffma2(w2p, h2.x, a2A); a2B = ffma2(w2p, h2.y, a2B);
            wp += WSTR; hidx += 2;
        }

        // combine k-halves (lane pair differs only in bit0)
        a0A = addx2(a0A, __shfl_xor_sync(0xFFFFFFFFu, a0A, 1));
        a0B = addx2(a0B, __shfl_xor_sync(0xFFFFFFFFu, a0B, 1));
        a1A = addx2(a1A, __shfl_xor_sync(0xFFFFFFFFu, a1A, 1));
        a1B = addx2(a1B, __shfl_xor_sync(0xFFFFFFFFu, a1B, 1));
        a2A = addx2(a2A, __shfl_xor_sync(0xFFFFFFFFu, a2A, 1));
        a2B = addx2(a2B, __shfl_xor_sync(0xFFFFFFFFu, a2B, 1));

        // this lane finalizes its 2 batch rows
        unsigned long long tr = half ? a0B : a0A;
        unsigned long long tz = half ? a1B : a1A;
        unsigned long long tn = half ? a2B : a2A;
        float sr0, sr1, sz0, sz1, sn0, sn1;
        unpack2(tr, sr0, sr1);
        unpack2(tz, sz0, sz1);
        unpack2(tn, sn0, sn1);

        float2 hp = *(const float2*)(hbuf + cur * HB_STRIDE + hphys_my);

        float r0 = fsig(x0r + sr0 + bh0);
        float z0 = fsig(x0z + sz0 + bh1);
        float n0 = ftanh_(x0n + r0 * (sn0 + bh2));
        float hn0 = (1.f - z0) * n0 + z0 * hp.x;

        float r1 = fsig(x1r + sr1 + bh0);
        float z1 = fsig(x1z + sz1 + bh1);
        float n1 = ftanh_(x1n + r1 * (sn1 + bh2));
        float hn1 = (1.f - z1) * n1 + z1 * hp.y;

        // push the pair to all 4 CTAs' next-buffer (one b64 store per rank)
        unsigned long long hnp = pack2(hn0, hn1);
        uint32_t laddr = smem_u32(hbuf + nxt * HB_STRIDE + hphys_my);
#pragma unroll
        for (int p = 0; p < 4; p++) {
            uint32_t raddr;
            asm volatile("mapa.shared::cluster.u32 %0, %1, %2;"
                         : "=r"(raddr) : "r"(laddr), "r"(p));
            asm volatile("st.shared::cluster.u64 [%0], %1;"
                         :: "r"(raddr), "l"(hnp) : "memory");
        }

        asm volatile("barrier.cluster.arrive.aligned;" ::: "memory");

        // global h writes overlap the barrier
        if (WRITE_ALL) {
            hout[((size_t)(b0 + myb) * SEQ + t) * HID + gu] = hn0;
            hout[((size_t)(b0 + myb + 1) * SEQ + t) * HID + gu] = hn1;
        } else if (t == SEQ - 1) {
            hout[(b0 + myb) * HID + gu] = hn0;
            hout[(b0 + myb + 1) * HID + gu] = hn1;
        }

        asm volatile("barrier.cluster.wait.aligned;" ::: "memory");
    }
}

// =======================================================================
// Final projection + 96-step linear state-space decode. 1 block per batch row.
// =======================================================================
__global__ void final_kernel(const float* __restrict__ hfin, const float* __restrict__ Wp,
                             const float* __restrict__ bp, const float* __restrict__ Cm,
                             const float* __restrict__ rld, const float* __restrict__ rtd,
                             const float* __restrict__ rg, const float* __restrict__ om,
                             float* __restrict__ out) {
    __shared__ float hs[256];
    __shared__ float ss[128];
    const int b = blockIdx.x, tid = threadIdx.x;  // 128 threads
    hs[tid]       = hfin[b * 256 + tid];
    hs[tid + 128] = hfin[b * 256 + 128 + tid];
    __syncthreads();

    float acc = bp[tid];
    const float* w = Wp + tid * 256;
#pragma unroll 8
    for (int k = 0; k < 256; k++) acc += w[k] * hs[k];
    ss[tid] = acc;
    __syncthreads();

    if (tid < 32) {
        const int d = tid;
        float s0 = ss[d * 4 + 0], s1 = ss[d * 4 + 1], s2 = ss[d * 4 + 2], s3 = ss[d * 4 + 3];
        const float al = 1.f / (1.f + expf(-rld[d])) * 0.15f + 0.85f;
        const float at = 1.f / (1.f + expf(-rtd[d])) * 0.25f + 0.70f;
        const float g  = 1.f / (1.f + expf(-rg[d]))  * 0.20f + 0.80f;
        const float c = cosf(om[d]), sn = sinf(om[d]);
        const float r00 = g * c, r01 = -g * sn, r10 = g * sn, r11 = g * c;
        const float C0 = Cm[d * 4 + 0], C1 = Cm[d * 4 + 1];
        const float C2 = Cm[d * 4 + 2], C3 = Cm[d * 4 + 3];
        float* ob = out + (size_t)b * PREDL * 32 + d;
#pragma unroll 4
        for (int t = 0; t < PREDL; t++) {
            float n0 = s0 * al;
            float n1 = s1 * at;
            float n2 = s2 * r00 + s3 * r10;
            float n3 = s2 * r01 + s3 * r11;
            ob[t * 32] = C0 * n0 + C1 * n1 + C2 * n2 + C3 * n3;
            s0 = n0; s1 = n1; s2 = n2; s3 = n3;
        }
    }
}

// =======================================================================
extern "C" void kernel_launch(void* const* d_in, const int* in_sizes, int n_in,
                              void* d_out, int out_size) {
    const float* x     = (const float*)d_in[0];
    const float* Wih0  = (const float*)d_in[1];
    const float* Whh0  = (const float*)d_in[2];
    const float* bih0  = (const float*)d_in[3];
    const float* bhh0  = (const float*)d_in[4];
    const float* Wih1  = (const float*)d_in[5];
    const float* Whh1  = (const float*)d_in[6];
    const float* bih1  = (const float*)d_in[7];
    const float* bhh1  = (const float*)d_in[8];
    const float* Wproj = (const float*)d_in[9];
    const float* bproj = (const float*)d_in[10];
    const float* Cm    = (const float*)d_in[11];
    const float* rld   = (const float*)d_in[12];
    const float* rtd   = (const float*)d_in[13];
    const float* rg    = (const float*)d_in[14];
    const float* om    = (const float*)d_in[15];
    float* out = (float*)d_out;

    float *xp0, *xp1, *h1, *hfin;
    cudaGetSymbolAddress((void**)&xp0,  g_xp0);
    cudaGetSymbolAddress((void**)&xp1,  g_xp1);
    cudaGetSymbolAddress((void**)&h1,   g_h1);
    cudaGetSymbolAddress((void**)&hfin, g_hfin);

    cudaFuncSetAttribute(gru_layer<true>,  cudaFuncAttributeMaxDynamicSharedMemorySize, GRU_SMEM_BYTES);
    cudaFuncSetAttribute(gru_layer<false>, cudaFuncAttributeMaxDynamicSharedMemorySize, GRU_SMEM_BYTES);

    const int M = BATCH * SEQ;  // 131072
    dim3 ggrid(G3 / 64, M / 64);

    // Phase 1: layer-0 input projection (K=32)
    gemm_bias<<<ggrid, 256>>>(x, Wih0, bih0, xp0, M, G3, INDIM);
    // Phase 2: layer-0 recurrence, write all h1
    gru_layer<true><<<128, 256, GRU_SMEM_BYTES>>>(xp0, Whh0, bhh0, h1);
    // Phase 3: layer-1 input projection (K=256)
    gemm_bias<<<ggrid, 256>>>(h1, Wih1, bih1, xp1, M, G3, HID);
    // Phase 4: layer-1 recurrence, final h only
    gru_layer<false><<<128, 256, GRU_SMEM_BYTES>>>(xp1, Whh1, bhh1, hfin);
    // Phase 5: projection + decode scan
    final_kernel<<<256, 128>>>(hfin, Wproj, bproj, Cm, rld, rtd, rg, om, out);
}

// round 8
// speedup vs baseline: 1.6927x; 1.0252x over previous
#include <cuda_runtime.h>
#include <cstdint>
#include <math.h>

// Problem dims
#define BATCH 256
#define SEQ   512
#define INDIM 32
#define HID   256
#define G3    768      // 3*HID
#define PREDL 96

// ---------------- scratch (static device memory; no allocation) ----------------
__device__ float g_xp0[(size_t)BATCH * SEQ * G3];   // x @ W_ih_l0^T + b_ih_l0
__device__ float g_xp1[(size_t)BATCH * SEQ * G3];   // h1 @ W_ih_l1^T + b_ih_l1
__device__ float g_h1 [(size_t)BATCH * SEQ * HID];  // layer-0 hidden states
__device__ float g_hfin[BATCH * HID];               // final hidden of layer 1

// ---------------- f32x2 packed helpers ----------------
__device__ __forceinline__ unsigned long long pack2(float lo, float hi) {
    unsigned long long r;
    asm("mov.b64 %0, {%1,%2};" : "=l"(r) : "f"(lo), "f"(hi));
    return r;
}
__device__ __forceinline__ void unpack2(unsigned long long v, float& lo, float& hi) {
    asm("mov.b64 {%0,%1}, %2;" : "=f"(lo), "=f"(hi) : "l"(v));
}
__device__ __forceinline__ unsigned long long ffma2(unsigned long long a,
                                                    unsigned long long b,
                                                    unsigned long long c) {
    unsigned long long d;
    asm("fma.rn.f32x2 %0, %1, %2, %3;" : "=l"(d) : "l"(a), "l"(b), "l"(c));
    return d;
}

__device__ __forceinline__ float fsig(float x) {
    return __fdividef(1.f, 1.f + __expf(-x));
}
__device__ __forceinline__ float ftanh_(float x) {
    // 1 - 2/(e^{2x}+1): saturates correctly at both ends (no inf/inf)
    return 1.f - __fdividef(2.f, __expf(2.f * x) + 1.f);
}

// =======================================================================
// Generic tiled GEMM:  C[M,N] = A[M,K] @ W[N,K]^T + bias[N]   (fp32, FFMA2)
// 64x64 block tile, 4x4 per thread, 256 threads.  (unchanged from R7)
// =======================================================================
__global__ void gemm_bias(const float* __restrict__ A, const float* __restrict__ W,
                          const float* __restrict__ bias, float* __restrict__ C,
                          int M, int N, int K) {
    __shared__ float As[16][68];
    __shared__ float Bs[16][68];
    const int n0 = blockIdx.x * 64;
    const int m0 = blockIdx.y * 64;
    const int tid = threadIdx.x;
    const int tx = tid & 15, ty = tid >> 4;

    unsigned long long accp[4][2];
#pragma unroll
    for (int i = 0; i < 4; i++) { accp[i][0] = 0ull; accp[i][1] = 0ull; }

    for (int k0 = 0; k0 < K; k0 += 16) {
#pragma unroll
        for (int i = tid; i < 1024; i += 256) {
            int r = i >> 4, c = i & 15;
            As[c][r] = A[(size_t)(m0 + r) * K + k0 + c];
            Bs[c][r] = W[(size_t)(n0 + r) * K + k0 + c];
        }
        __syncthreads();
#pragma unroll
        for (int kk = 0; kk < 16; kk++) {
            float4 av = *(const float4*)&As[kk][ty * 4];
            ulonglong2 bv = *(const ulonglong2*)&Bs[kk][tx * 4];
            unsigned long long ap0 = pack2(av.x, av.x);
            unsigned long long ap1 = pack2(av.y, av.y);
            unsigned long long ap2 = pack2(av.z, av.z);
            unsigned long long ap3 = pack2(av.w, av.w);
            accp[0][0] = ffma2(ap0, bv.x, accp[0][0]); accp[0][1] = ffma2(ap0, bv.y, accp[0][1]);
            accp[1][0] = ffma2(ap1, bv.x, accp[1][0]); accp[1][1] = ffma2(ap1, bv.y, accp[1][1]);
            accp[2][0] = ffma2(ap2, bv.x, accp[2][0]); accp[2][1] = ffma2(ap2, bv.y, accp[2][1]);
            accp[3][0] = ffma2(ap3, bv.x, accp[3][0]); accp[3][1] = ffma2(ap3, bv.y, accp[3][1]);
        }
        __syncthreads();
    }
#pragma unroll
    for (int i = 0; i < 4; i++) {
        int m = m0 + ty * 4 + i;
        float a0, a1, a2, a3;
        unpack2(accp[i][0], a0, a1);
        unpack2(accp[i][1], a2, a3);
        int n = n0 + tx * 4;
        float* cp = C + (size_t)m * N + n;
        cp[0] = a0 + bias[n + 0];
        cp[1] = a1 + bias[n + 1];
        cp[2] = a2 + bias[n + 2];
        cp[3] = a3 + bias[n + 3];
    }
}

// =======================================================================
// GRU recurrence v3.
// Cluster of 4 CTAs covers 256 hidden units (64 per CTA). 8 batch / cluster.
// 256 threads/CTA: kq = tid&3 (k-quarter of 64), u = tid>>2 (unit 0..63).
// Each thread: 3 gates x 8 batch over its 64-k quarter, k-pair FFMA2
// (both operands natural 64-bit pairs, no packing). W read exactly once
// per SM per step. kq-reduction via warp bfly; each lane finalizes
// batches {2kq, 2kq+1} and pushes them to all 4 CTAs via DSMEM.
//
// W SMEM: kq-major blocks of 13064 words (192 rows x 68 + 8 pad).
//   phys(row,k) = (k>>6)*13064 + row*68 + (k&63)
//   bank slot within a phase-group: (u + 2*kq) mod 8  -> conflict-free.
// h SMEM: [2 buf][8 batch][276 words]; h[b][k] at b*276 + (k>>6)*68 + (k&63)
//   -> 4-address broadcast LDS.128, banks disjoint (kq spaced 4 banks).
// =======================================================================
#define WBLK  13064
#define WT_WORDS (4 * WBLK)             // 52256
#define HSTR  276
#define HBUF_WORDS (8 * HSTR)           // 2208 per buffer
#define GRU_SMEM_FLOATS (WT_WORDS + 2 * HBUF_WORDS)
#define GRU_SMEM_BYTES  (GRU_SMEM_FLOATS * 4)   // 226,688 B

__device__ __forceinline__ uint32_t smem_u32(const void* p) {
    return (uint32_t)__cvta_generic_to_shared(p);
}

template <bool WRITE_ALL>
__global__ __launch_bounds__(256, 1) __cluster_dims__(4, 1, 1)
void gru_layer(const float* __restrict__ xp, const float* __restrict__ W_hh,
               const float* __restrict__ b_hh, float* __restrict__ hout) {
    extern __shared__ float smem[];
    float* Wt   = smem;                 // WT_WORDS
    float* hbuf = smem + WT_WORDS;      // 2 * HBUF_WORDS

    const int tid = threadIdx.x;
    const int kq  = tid & 3;
    const int u   = tid >> 2;           // 0..63
    uint32_t rank;
    asm("mov.u32 %0, %%cluster_ctarank;" : "=r"(rank));
    const int gu  = (int)rank * 64 + u;
    const int b0  = (blockIdx.x >> 2) * 8;
    const int myb = 2 * kq;             // this lane finalizes batches myb, myb+1

    // Load W_hh slice into kq-blocked layout (coalesced over k).
    for (int idx = tid; idx < 192 * 256; idx += 256) {
        int row = idx >> 8, k = idx & 255;
        int grow = ((row >> 6) << 8) + (int)rank * 64 + (row & 63);
        Wt[(k >> 6) * WBLK + row * 68 + (k & 63)] = W_hh[grow * 256 + k];
    }
    for (int i = tid; i < 2 * HBUF_WORDS; i += 256) hbuf[i] = 0.f;

    const float bh0 = b_hh[gu], bh1 = b_hh[256 + gu], bh2 = b_hh[512 + gu];

    // running global pointers for this lane's 2 batch rows of xp
    const float* pxa = xp + ((size_t)(b0 + myb) * SEQ) * G3 + gu;
    const float* pxb = pxa + (size_t)SEQ * G3;

    // epilogue h-read / push physical offset of h[b][gu] (per buffer)
    const int hoff_my = myb * HSTR + (int)rank * 68 + u;

    // all CTAs' hbuf init done before anyone pushes / reads
    asm volatile("barrier.cluster.arrive.aligned;" ::: "memory");
    asm volatile("barrier.cluster.wait.aligned;" ::: "memory");

    for (int t = 0; t < SEQ; t++) {
        const int cur = t & 1, nxt = cur ^ 1;

        // prefetch input projections (hidden under the k-loop)
        float xa_r = pxa[0], xa_z = pxa[256], xa_n = pxa[512];
        float xb_r = pxb[0], xb_z = pxb[256], xb_n = pxb[512];
        pxa += G3; pxb += G3;

        unsigned long long acc[3][8];
#pragma unroll
        for (int g = 0; g < 3; g++)
#pragma unroll
            for (int b = 0; b < 8; b++) acc[g][b] = 0ull;

        const float* wbase = Wt + kq * WBLK + u * 68;
        const float* hb    = hbuf + cur * HBUF_WORDS + kq * 68;

#pragma unroll 4
        for (int c = 0; c < 16; c++) {
            const int kl = c * 4;
            ulonglong2 w0 = *(const ulonglong2*)(wbase + kl);           // gate r
            ulonglong2 w1 = *(const ulonglong2*)(wbase + 4352 + kl);    // gate z
            ulonglong2 w2 = *(const ulonglong2*)(wbase + 8704 + kl);    // gate n
#pragma unroll
            for (int b = 0; b < 8; b++) {
                ulonglong2 h2 = *(const ulonglong2*)(hb + b * HSTR + kl);
                acc[0][b] = ffma2(w0.x, h2.x, acc[0][b]);
                acc[0][b] = ffma2(w0.y, h2.y, acc[0][b]);
                acc[1][b] = ffma2(w1.x, h2.x, acc[1][b]);
                acc[1][b] = ffma2(w1.y, h2.y, acc[1][b]);
                acc[2][b] = ffma2(w2.x, h2.x, acc[2][b]);
                acc[2][b] = ffma2(w2.y, h2.y, acc[2][b]);
            }
        }

        // collapse k-parity, then reduce across the 4 kq lanes (bits 0-1)
        float s[3][8];
#pragma unroll
        for (int g = 0; g < 3; g++)
#pragma unroll
            for (int b = 0; b < 8; b++) {
                float lo, hi;
                unpack2(acc[g][b], lo, hi);
                float v = lo + hi;
                v += __shfl_xor_sync(0xFFFFFFFFu, v, 1);
                v += __shfl_xor_sync(0xFFFFFFFFu, v, 2);
                s[g][b] = v;
            }

        // select this lane's 2 batches (myb = 2*kq) without dynamic indexing
        const bool q1 = (kq & 1), q2 = (kq & 2);
        float sA[3], sB[3];
#pragma unroll
        for (int g = 0; g < 3; g++) {
            float loA = q1 ? s[g][2] : s[g][0];
            float hiA = q1 ? s[g][6] : s[g][4];
            sA[g] = q2 ? hiA : loA;
            float loB = q1 ? s[g][3] : s[g][1];
            float hiB = q1 ? s[g][7] : s[g][5];
            sB[g] = q2 ? hiB : loB;
        }

        float hpA = hbuf[cur * HBUF_WORDS + hoff_my];
        float hpB = hbuf[cur * HBUF_WORDS + hoff_my + HSTR];

        float rA = fsig(xa_r + sA[0] + bh0);
        float zA = fsig(xa_z + sA[1] + bh1);
        float nA = ftanh_(xa_n + rA * (sA[2] + bh2));
        float hnA = (1.f - zA) * nA + zA * hpA;

        float rB = fsig(xb_r + sB[0] + bh0);
        float zB = fsig(xb_z + sB[1] + bh1);
        float nB = ftanh_(xb_n + rB * (sB[2] + bh2));
        float hnB = (1.f - zB) * nB + zB * hpB;

        // push both batches to all 4 CTAs' next buffer
        uint32_t laddrA = smem_u32(hbuf + nxt * HBUF_WORDS + hoff_my);
#pragma unroll
        for (int p = 0; p < 4; p++) {
            uint32_t ra;
            asm volatile("mapa.shared::cluster.u32 %0, %1, %2;"
                         : "=r"(ra) : "r"(laddrA), "r"(p));
            asm volatile("st.shared::cluster.f32 [%0], %1;"
                         :: "r"(ra), "f"(hnA) : "memory");
            asm volatile("st.shared::cluster.f32 [%0+1104], %1;"   // +HSTR*4 bytes
                         :: "r"(ra), "f"(hnB) : "memory");
        }

        asm volatile("barrier.cluster.arrive.aligned;" ::: "memory");

        // global h writes overlap the barrier
        if (WRITE_ALL) {
            hout[((size_t)(b0 + myb) * SEQ + t) * HID + gu] = hnA;
            hout[((size_t)(b0 + myb + 1) * SEQ + t) * HID + gu] = hnB;
        } else if (t == SEQ - 1) {
            hout[(b0 + myb) * HID + gu] = hnA;
            hout[(b0 + myb + 1) * HID + gu] = hnB;
        }

        asm volatile("barrier.cluster.wait.aligned;" ::: "memory");
    }
}

// =======================================================================
// Final projection + 96-step linear state-space decode. 1 block per batch row.
// =======================================================================
__global__ void final_kernel(const float* __restrict__ hfin, const float* __restrict__ Wp,
                             const float* __restrict__ bp, const float* __restrict__ Cm,
                             const float* __restrict__ rld, const float* __restrict__ rtd,
                             const float* __restrict__ rg, const float* __restrict__ om,
                             float* __restrict__ out) {
    __shared__ float hs[256];
    __shared__ float ss[128];
    const int b = blockIdx.x, tid = threadIdx.x;  // 128 threads
    hs[tid]       = hfin[b * 256 + tid];
    hs[tid + 128] = hfin[b * 256 + 128 + tid];
    __syncthreads();

    float acc = bp[tid];
    const float* w = Wp + tid * 256;
#pragma unroll 8
    for (int k = 0; k < 256; k++) acc += w[k] * hs[k];
    ss[tid] = acc;
    __syncthreads();

    if (tid < 32) {
        const int d = tid;
        float s0 = ss[d * 4 + 0], s1 = ss[d * 4 + 1], s2 = ss[d * 4 + 2], s3 = ss[d * 4 + 3];
        const float al = 1.f / (1.f + expf(-rld[d])) * 0.15f + 0.85f;
        const float at = 1.f / (1.f + expf(-rtd[d])) * 0.25f + 0.70f;
        const float g  = 1.f / (1.f + expf(-rg[d]))  * 0.20f + 0.80f;
        const float c = cosf(om[d]), sn = sinf(om[d]);
        const float r00 = g * c, r01 = -g * sn, r10 = g * sn, r11 = g * c;
        const float C0 = Cm[d * 4 + 0], C1 = Cm[d * 4 + 1];
        const float C2 = Cm[d * 4 + 2], C3 = Cm[d * 4 + 3];
        float* ob = out + (size_t)b * PREDL * 32 + d;
#pragma unroll 4
        for (int t = 0; t < PREDL; t++) {
            float n0 = s0 * al;
            float n1 = s1 * at;
            float n2 = s2 * r00 + s3 * r10;
            float n3 = s2 * r01 + s3 * r11;
            ob[t * 32] = C0 * n0 + C1 * n1 + C2 * n2 + C3 * n3;
            s0 = n0; s1 = n1; s2 = n2; s3 = n3;
        }
    }
}

// =======================================================================
extern "C" void kernel_launch(void* const* d_in, const int* in_sizes, int n_in,
                              void* d_out, int out_size) {
    const float* x     = (const float*)d_in[0];
    const float* Wih0  = (const float*)d_in[1];
    const float* Whh0  = (const float*)d_in[2];
    const float* bih0  = (const float*)d_in[3];
    const float* bhh0  = (const float*)d_in[4];
    const float* Wih1  = (const float*)d_in[5];
    const float* Whh1  = (const float*)d_in[6];
    const float* bih1  = (const float*)d_in[7];
    const float* bhh1  = (const float*)d_in[8];
    const float* Wproj = (const float*)d_in[9];
    const float* bproj = (const float*)d_in[10];
    const float* Cm    = (const float*)d_in[11];
    const float* rld   = (const float*)d_in[12];
    const float* rtd   = (const float*)d_in[13];
    const float* rg    = (const float*)d_in[14];
    const float* om    = (const float*)d_in[15];
    float* out = (float*)d_out;

    float *xp0, *xp1, *h1, *hfin;
    cudaGetSymbolAddress((void**)&xp0,  g_xp0);
    cudaGetSymbolAddress((void**)&xp1,  g_xp1);
    cudaGetSymbolAddress((void**)&h1,   g_h1);
    cudaGetSymbolAddress((void**)&hfin, g_hfin);

    cudaFuncSetAttribute(gru_layer<true>,  cudaFuncAttributeMaxDynamicSharedMemorySize, GRU_SMEM_BYTES);
    cudaFuncSetAttribute(gru_layer<false>, cudaFuncAttributeMaxDynamicSharedMemorySize, GRU_SMEM_BYTES);

    const int M = BATCH * SEQ;  // 131072
    dim3 ggrid(G3 / 64, M / 64);

    // Phase 1: layer-0 input projection (K=32)
    gemm_bias<<<ggrid, 256>>>(x, Wih0, bih0, xp0, M, G3, INDIM);
    // Phase 2: layer-0 recurrence, write all h1
    gru_layer<true><<<128, 256, GRU_SMEM_BYTES>>>(xp0, Whh0, bhh0, h1);
    // Phase 3: layer-1 input projection (K=256)
    gemm_bias<<<ggrid, 256>>>(h1, Wih1, bih1, xp1, M, G3, HID);
    // Phase 4: layer-1 recurrence, final h only
    gru_layer<false><<<128, 256, GRU_SMEM_BYTES>>>(xp1, Whh1, bhh1, hfin);
    // Phase 5: projection + decode scan
    final_kernel<<<256, 128>>>(hfin, Wproj, bproj, Cm, rld, rtd, rg, om, out);
}